// round 8
// baseline (speedup 1.0000x reference)
#include <cuda_runtime.h>
#include <cuda_bf16.h>

#define LLEN 1024
#define DD   128
#define EPSF 1e-5f
#define LP   4
#define NTILE 512     // 256 l-tiles x 2 d-halves
#define BUFB 53248    // bytes per round buffer: Ah 17408 + Am 17408 + Bh 9216 + Bm 9216

// ---------------- scratch (device globals; no allocation) ----------------
__device__ float    g_a  [LLEN * DD];
__device__ float    g_tx [LLEN * DD];
__device__ float    g_Rp [4 * LLEN * DD];
__device__ float    g_o1 [LLEN * DD];
__device__ unsigned g_ah [512 * DD];
__device__ unsigned g_am [512 * DD];
__device__ unsigned g_bh [512 * DD];
__device__ unsigned g_bm [512 * DD];
__device__ unsigned g_mkp[LLEN * 512];
__device__ unsigned g_tile_ctr;

// ---------------- helpers ----------------
__device__ __forceinline__ unsigned smem_u32(const void* p) {
    unsigned a;
    asm("{ .reg .u64 t; cvta.to.shared.u64 t, %1; cvt.u32.u64 %0, t; }" : "=r"(a) : "l"(p));
    return a;
}
#define CP_ASYNC16(dst, src) \
    asm volatile("cp.async.cg.shared.global [%0], [%1], 16;" :: "r"(dst), "l"(src))
#define CP_COMMIT() asm volatile("cp.async.commit_group;" ::: "memory")
#define CP_WAIT0()  asm volatile("cp.async.wait_group 0;" ::: "memory")

__device__ __forceinline__ unsigned pack_bf16x2(float lo, float hi) {
    unsigned u;
    asm("cvt.rn.bf16x2.f32 %0, %1, %2;" : "=r"(u) : "f"(hi), "f"(lo));
    return u;
}
__device__ __forceinline__ void split_bf16(float x0, float x1, unsigned& uh, unsigned& um) {
    uh = pack_bf16x2(x0, x1);
    float h0 = __uint_as_float(uh << 16);
    float h1 = __uint_as_float(uh & 0xFFFF0000u);
    um = pack_bf16x2(x0 - h0, x1 - h1);
}
__device__ __forceinline__ void mma_bf16(float* c, unsigned a0, unsigned a1, unsigned a2,
                                         unsigned a3, unsigned b0, unsigned b1) {
    asm volatile(
        "mma.sync.aligned.m16n8k16.row.col.f32.bf16.bf16.f32 "
        "{%0,%1,%2,%3}, {%4,%5,%6,%7}, {%8,%9}, {%0,%1,%2,%3};"
        : "+f"(c[0]), "+f"(c[1]), "+f"(c[2]), "+f"(c[3])
        : "r"(a0), "r"(a1), "r"(a2), "r"(a3), "r"(b0), "r"(b1));
}

// ---------------- kernel 1: projections + fused bf16 split ----------------
__global__ __launch_bounds__(256) void proj_kernel(
    const float* __restrict__ x,
    const float* __restrict__ Wl,  const float* __restrict__ bl,
    const float* __restrict__ Wl2, const float* __restrict__ bl2)
{
    __shared__ float xs[8 * DD];
    __shared__ float ws[32 * 129];
    __shared__ float ys[8 * DD];
    const int t = threadIdx.x, l0 = blockIdx.x * 8;
    const int dloc = t & 31, lrow = t >> 5;
    for (int i = t; i < 8 * DD; i += 256) xs[i] = x[l0 * DD + i];
    for (int mat = 0; mat < 2; mat++) {
        const float* W    = mat ? Wl2 : Wl;
        const float* bias = mat ? bl2 : bl;
        float*       outp = mat ? g_tx : g_a;
        unsigned*    oh   = mat ? g_bh : g_ah;
        unsigned*    om   = mat ? g_bm : g_am;
        for (int dc = 0; dc < 4; dc++) {
            const int d0 = dc * 32;
            __syncthreads();
            for (int i = t; i < 32 * DD; i += 256) {
                int r = i >> 7, c = i & 127;
                ws[r * 129 + c] = W[(d0 + r) * DD + c];
            }
            __syncthreads();
            float acc = 0.f;
            #pragma unroll 8
            for (int c = 0; c < DD; c++) acc += xs[lrow * DD + c] * ws[dloc * 129 + c];
            acc += bias[d0 + dloc];
            outp[(l0 + lrow) * DD + d0 + dloc] = acc;
            ys[lrow * DD + d0 + dloc] = acc;
        }
        __syncthreads();
        #pragma unroll
        for (int i = 0; i < 2; i++) {
            int idx = t + 256 * i;
            int j = idx >> 7, c = idx & 127;
            float x0 = ys[(2 * j) * DD + c];
            float x1 = ys[(2 * j + 1) * DD + c];
            unsigned uh, um; split_bf16(x0, x1, uh, um);
            int kp = (l0 >> 1) + j;
            oh[kp * DD + c] = uh; om[kp * DD + c] = um;
        }
    }
}

// ---------------- kernel 2: R partials + mask pair-words + ctr reset ----------------
__global__ __launch_bounds__(256) void r_kernel(const int* __restrict__ mask)
{
    __shared__ float s_txc[64 * DD];
    __shared__ float s_mk [16 * 64];
    const int t = threadIdx.x;
    const int l0 = blockIdx.x * 16;
    const int mg = blockIdx.y;
    const int d4 = t & 31, lg = t >> 5;
    if (blockIdx.x == 0 && mg == 0 && t == 0) g_tile_ctr = 0u;

    // mask pair-words for this (l-tile, m-group): 16 l x 128 kp
    #pragma unroll
    for (int i = 0; i < 8; i++) {
        int idx = t + 256 * i;                // 0..2047
        int li = idx >> 7, kpl = idx & 127;
        int kp = mg * 128 + kpl;
        int ma = mask[(l0 + li) * LLEN + 2 * kp];
        int mb = mask[(l0 + li) * LLEN + 2 * kp + 1];
        g_mkp[(l0 + li) * 512 + kp] = (ma ? 0x0000FFFFu : 0u) | (mb ? 0xFFFF0000u : 0u);
    }

    float4 a0 = {0.f,0.f,0.f,0.f}, a1 = {0.f,0.f,0.f,0.f};
    for (int ch = 0; ch < 4; ch++) {
        const int m0 = mg * 256 + ch * 64;
        __syncthreads();
        #pragma unroll
        for (int r = 0; r < 8; r++) {
            int idx = t + 256 * r;
            int rw = idx >> 5, c4 = idx & 31;
            *(float4*)&s_txc[rw * DD + c4 * 4] = *(const float4*)&g_tx[(m0 + rw) * DD + c4 * 4];
        }
        #pragma unroll
        for (int r = 0; r < 4; r++) {
            int idx = t + 256 * r;
            int li = idx >> 6, mm = idx & 63;
            s_mk[li * 64 + mm] = (mask[(l0 + li) * LLEN + m0 + mm] != 0) ? 1.f : 0.f;
        }
        __syncthreads();
        #pragma unroll 4
        for (int mm = 0; mm < 64; mm++) {
            float4 tv = *(float4*)&s_txc[mm * DD + d4 * 4];
            float f0 = s_mk[(lg * 2) * 64 + mm];
            float f1 = s_mk[(lg * 2 + 1) * 64 + mm];
            a0.x += tv.x * f0; a0.y += tv.y * f0; a0.z += tv.z * f0; a0.w += tv.w * f0;
            a1.x += tv.x * f1; a1.y += tv.y * f1; a1.z += tv.z * f1; a1.w += tv.w * f1;
        }
    }
    *(float4*)&g_Rp[(mg * LLEN + l0 + lg * 2) * DD + d4 * 4]     = a0;
    *(float4*)&g_Rp[(mg * LLEN + l0 + lg * 2 + 1) * DD + d4 * 4] = a1;
}

// ---------------- kernel 3: persistent mma.sync GEMM, cp.async double-buffer, KC=64 ----------------
// SMEM: s_a 0..2048, s_mk 2048..10240,
//   buf0 @10240, buf1 @63488; each: Ah(17408) Am(17408) Bh(9216) Bm(9216) = 53248
// Epilogue reuse: wlo@10240 (33792), ep@44032 (8192). Total dynamic = 116736.
__global__ __launch_bounds__(256, 1) void cop_kernel(const float* __restrict__ Wlo)
{
    extern __shared__ char sm[];
    float*    s_a   = (float*)sm;
    unsigned* s_mk  = (unsigned*)(sm + 2048);
    float*    s_wlo = (float*)(sm + 10240);
    float*    s_ep  = (float*)(sm + 44032);
    __shared__ int s_tile;
    const unsigned sb = smem_u32(sm);

    const int t    = threadIdx.x;
    const int w    = t >> 5;
    const int lane = t & 31;
    const int gid  = lane >> 2;
    const int tig  = lane & 3;
    const int ct0  = w * 16;

    // per-thread copy indices (KC=64: 32 m-pair rows per round)
    const int rowA = t >> 5;            // with i-stride 8 rows: rows rowA + 8*i? no: idx>>5
    const int c4A  = t & 31;
    const int rowB = t >> 4;            // idx>>4, i-stride 16 rows
    const int c4B  = t & 15;

    for (;;) {
        if (t == 0) s_tile = (int)atomicAdd(&g_tile_ctr, 1u);
        __syncthreads();                 // publishes s_tile; all warps done with prev tile smem
        const int tile = s_tile;
        if (tile >= NTILE) break;
        const int l0 = (tile >> 1) * LP;
        const int d0 = (tile & 1) * 64;

        // stage a_l + mask pair-words (read after the round-0 barrier)
        #pragma unroll
        for (int i = 0; i < 2; i++) {
            int idx = t + 256 * i;
            s_a[idx] = g_a[(l0 + (idx >> 7)) * DD + (idx & 127)];
        }
        #pragma unroll
        for (int i = 0; i < 8; i++) {
            int idx = t + 256 * i;
            s_mk[idx] = g_mkp[(l0 + (idx >> 9)) * 512 + (idx & 511)];
        }

        float acc[LP][8][4];
        #pragma unroll
        for (int l = 0; l < LP; l++)
            #pragma unroll
            for (int dg = 0; dg < 8; dg++)
                #pragma unroll
                for (int q = 0; q < 4; q++) acc[l][dg][q] = 0.f;

        // ---- issue round-0 copies ----
        {
            const unsigned bufu = sb + 10240;
            #pragma unroll
            for (int i = 0; i < 4; i++) {
                int idx = t + 256 * i;
                int rw = idx >> 5, c4 = idx & 31;
                const unsigned dsto = rw * 136 + c4 * 4;
                CP_ASYNC16(bufu + dsto * 4,         (const char*)(g_ah + rw * 128 + c4 * 4));
                CP_ASYNC16(bufu + 17408 + dsto * 4, (const char*)(g_am + rw * 128 + c4 * 4));
            }
            #pragma unroll
            for (int i = 0; i < 2; i++) {
                int idx = t + 256 * i;
                int rw = idx >> 4, c4 = idx & 15;
                const unsigned dsto = rw * 72 + c4 * 4;
                CP_ASYNC16(bufu + 34816 + dsto * 4, (const char*)(g_bh + rw * 128 + d0 + c4 * 4));
                CP_ASYNC16(bufu + 44032 + dsto * 4, (const char*)(g_bm + rw * 128 + d0 + c4 * 4));
            }
            CP_COMMIT();
        }

        #pragma unroll 1
        for (int r = 0; r < 16; r++) {
            CP_WAIT0();          // this thread's round-r copies landed
            __syncthreads();     // everyone's landed; prev round's reads done
            if (r < 15) {        // issue round r+1 into the other buffer
                const int kg = (r + 1) * 32;
                const unsigned bufu = sb + 10240 + ((r + 1) & 1) * BUFB;
                #pragma unroll
                for (int i = 0; i < 4; i++) {
                    int idx = t + 256 * i;
                    int rw = idx >> 5, c4 = idx & 31;
                    const unsigned dsto = rw * 136 + c4 * 4;
                    const unsigned srco = (kg + rw) * 128 + c4 * 4;
                    CP_ASYNC16(bufu + dsto * 4,         (const char*)(g_ah + srco));
                    CP_ASYNC16(bufu + 17408 + dsto * 4, (const char*)(g_am + srco));
                }
                #pragma unroll
                for (int i = 0; i < 2; i++) {
                    int idx = t + 256 * i;
                    int rw = idx >> 4, c4 = idx & 15;
                    const unsigned dsto = rw * 72 + c4 * 4;
                    const unsigned srco = (kg + rw) * 128 + d0 + c4 * 4;
                    CP_ASYNC16(bufu + 34816 + dsto * 4, (const char*)(g_bh + srco));
                    CP_ASYNC16(bufu + 44032 + dsto * 4, (const char*)(g_bm + srco));
                }
                CP_COMMIT();
            }
            char* buf = sm + 10240 + (r & 1) * BUFB;
            unsigned* sAh = (unsigned*)(buf);
            unsigned* sAm = (unsigned*)(buf + 17408);
            unsigned* sBh = (unsigned*)(buf + 34816);
            unsigned* sBm = (unsigned*)(buf + 44032);
            const int kpg = r * 32;
            #pragma unroll
            for (int s = 0; s < 4; s++) {
                const int kb = 8 * s;
                unsigned ah0 = sAh[(kb + tig) * 136 + ct0 + gid];
                unsigned ah1 = sAh[(kb + tig) * 136 + ct0 + gid + 8];
                unsigned ah2 = sAh[(kb + tig + 4) * 136 + ct0 + gid];
                unsigned ah3 = sAh[(kb + tig + 4) * 136 + ct0 + gid + 8];
                unsigned am0 = sAm[(kb + tig) * 136 + ct0 + gid];
                unsigned am1 = sAm[(kb + tig) * 136 + ct0 + gid + 8];
                unsigned am2 = sAm[(kb + tig + 4) * 136 + ct0 + gid];
                unsigned am3 = sAm[(kb + tig + 4) * 136 + ct0 + gid + 8];
                unsigned mkl[LP], mkh[LP];
                #pragma unroll
                for (int l = 0; l < LP; l++) {
                    mkl[l] = s_mk[l * 512 + kpg + kb + tig];
                    mkh[l] = s_mk[l * 512 + kpg + kb + tig + 4];
                }
                unsigned b0[8], b1[8];
                #pragma unroll
                for (int dg = 0; dg < 8; dg++) {
                    b0[dg] = sBh[(kb + tig) * 72 + dg * 8 + gid];
                    b1[dg] = sBh[(kb + tig + 4) * 72 + dg * 8 + gid];
                }
                #pragma unroll
                for (int l = 0; l < LP; l++) {      // hh
                    unsigned x0 = ah0 & mkl[l], x1 = ah1 & mkl[l];
                    unsigned x2 = ah2 & mkh[l], x3 = ah3 & mkh[l];
                    #pragma unroll
                    for (int dg = 0; dg < 8; dg++)
                        mma_bf16(acc[l][dg], x0, x1, x2, x3, b0[dg], b1[dg]);
                }
                #pragma unroll
                for (int l = 0; l < LP; l++) {      // mh
                    unsigned x0 = am0 & mkl[l], x1 = am1 & mkl[l];
                    unsigned x2 = am2 & mkh[l], x3 = am3 & mkh[l];
                    #pragma unroll
                    for (int dg = 0; dg < 8; dg++)
                        mma_bf16(acc[l][dg], x0, x1, x2, x3, b0[dg], b1[dg]);
                }
                #pragma unroll
                for (int dg = 0; dg < 8; dg++) {
                    b0[dg] = sBm[(kb + tig) * 72 + dg * 8 + gid];
                    b1[dg] = sBm[(kb + tig + 4) * 72 + dg * 8 + gid];
                }
                #pragma unroll
                for (int l = 0; l < LP; l++) {      // hm
                    unsigned x0 = ah0 & mkl[l], x1 = ah1 & mkl[l];
                    unsigned x2 = ah2 & mkh[l], x3 = ah3 & mkh[l];
                    #pragma unroll
                    for (int dg = 0; dg < 8; dg++)
                        mma_bf16(acc[l][dg], x0, x1, x2, x3, b0[dg], b1[dg]);
                }
            }
        }

        // ---- epilogue: sum_c a_l[c]*Wlo[d,c]*H ----
        __syncthreads();
        #pragma unroll
        for (int i = 0; i < 32; i++) {
            int idx = t + 256 * i;
            int dd = idx >> 7, c = idx & 127;
            s_wlo[dd * 132 + c] = Wlo[(d0 + dd) * DD + c];
        }
        __syncthreads();

        const int cA = ct0 + gid, cB = cA + 8;
        #pragma unroll
        for (int l = 0; l < LP; l++) {
            const float aA = s_a[l * DD + cA];
            const float aB = s_a[l * DD + cB];
            float pd[16];
            #pragma unroll
            for (int dg = 0; dg < 8; dg++) {
                const int dl0 = dg * 8 + 2 * tig;
                float w0  = s_wlo[dl0 * 132 + cA],  w1  = s_wlo[(dl0 + 1) * 132 + cA];
                float w0b = s_wlo[dl0 * 132 + cB],  w1b = s_wlo[(dl0 + 1) * 132 + cB];
                pd[2 * dg]     = acc[l][dg][0] * (aA * w0) + acc[l][dg][2] * (aB * w0b);
                pd[2 * dg + 1] = acc[l][dg][1] * (aA * w1) + acc[l][dg][3] * (aB * w1b);
            }
            #pragma unroll
            for (int off = 16; off >= 4; off >>= 1)
                #pragma unroll
                for (int q = 0; q < 16; q++)
                    pd[q] += __shfl_down_sync(0xffffffffu, pd[q], off);
            if (lane < 4) {
                #pragma unroll
                for (int dg = 0; dg < 8; dg++) {
                    s_ep[w * 256 + l * 64 + dg * 8 + 2 * lane]     = pd[2 * dg];
                    s_ep[w * 256 + l * 64 + dg * 8 + 2 * lane + 1] = pd[2 * dg + 1];
                }
            }
        }
        __syncthreads();
        {
            const int l = t >> 6, dloc = t & 63;
            float v = s_ep[t] + s_ep[256 + t] + s_ep[512 + t] + s_ep[768 + t]
                    + s_ep[1024 + t] + s_ep[1280 + t] + s_ep[1536 + t] + s_ep[1792 + t];
            g_o1[(l0 + l) * DD + d0 + dloc] = v;
        }
    }
}

// ---------------- kernel 4: residual + blo*R + LayerNorm ----------------
__global__ __launch_bounds__(128) void ln_kernel(
    const float* __restrict__ x,   const float* __restrict__ blo,
    const float* __restrict__ gamma, const float* __restrict__ beta,
    float* __restrict__ out)
{
    __shared__ float w1[4], w2[4];
    __shared__ float mu_s, rstd_s;
    const int l = blockIdx.x;
    const int d = threadIdx.x;
    float Rv = g_Rp[l * DD + d] + g_Rp[(LLEN + l) * DD + d]
             + g_Rp[(2 * LLEN + l) * DD + d] + g_Rp[(3 * LLEN + l) * DD + d];
    float y = x[l * DD + d] + g_o1[l * DD + d] + blo[d] * Rv;
    float s1 = y, s2 = y * y;
    #pragma unroll
    for (int off = 16; off > 0; off >>= 1) {
        s1 += __shfl_down_sync(0xffffffffu, s1, off);
        s2 += __shfl_down_sync(0xffffffffu, s2, off);
    }
    const int wid = d >> 5, lid = d & 31;
    if (lid == 0) { w1[wid] = s1; w2[wid] = s2; }
    __syncthreads();
    if (d == 0) {
        float t1 = w1[0] + w1[1] + w1[2] + w1[3];
        float t2 = w2[0] + w2[1] + w2[2] + w2[3];
        float mu = t1 * (1.f / DD);
        float var = t2 * (1.f / DD) - mu * mu;
        mu_s = mu; rstd_s = rsqrtf(var + EPSF);
    }
    __syncthreads();
    out[l * DD + d] = (y - mu_s) * rstd_s * gamma[d] + beta[d];
}

// ---------------- launch ----------------
extern "C" void kernel_launch(void* const* d_in, const int* in_sizes, int n_in,
                              void* d_out, int out_size)
{
    (void)in_sizes; (void)n_in; (void)out_size;
    const float* x     = (const float*)d_in[0];
    const int*   mask  = (const int*)  d_in[1];
    const float* Wl    = (const float*)d_in[2];
    const float* bl    = (const float*)d_in[3];
    const float* Wlo   = (const float*)d_in[4];
    const float* blo   = (const float*)d_in[5];
    const float* Wl2   = (const float*)d_in[6];
    const float* bl2   = (const float*)d_in[7];
    const float* gamma = (const float*)d_in[8];
    const float* beta  = (const float*)d_in[9];
    float* out = (float*)d_out;

    static int smem_set = 0;
    if (!smem_set) {
        cudaFuncSetAttribute(cop_kernel, cudaFuncAttributeMaxDynamicSharedMemorySize, 116736);
        smem_set = 1;
    }

    proj_kernel<<<128, 256>>>(x, Wl, bl, Wl2, bl2);        // 1
    r_kernel<<<dim3(64, 4), 256>>>(mask);                  // 2
    cop_kernel<<<148, 256, 116736>>>(Wlo);                 // 3
    ln_kernel<<<1024, 128>>>(x, blo, gamma, beta, out);    // 4
}

// round 9
// speedup vs baseline: 1.0849x; 1.0849x over previous
#include <cuda_runtime.h>
#include <cuda_bf16.h>

#define LLEN 1024
#define DD   128
#define EPSF 1e-5f
#define LP   4
#define NTILE 512     // 256 l-tiles x 2 d-halves
#define BUFB 53248    // bytes per round buffer: Ah 17408 + Am 17408 + Bh 9216 + Bm 9216

// ---------------- scratch (device globals; no allocation) ----------------
__device__ float    g_a  [LLEN * DD];
__device__ float    g_tx [LLEN * DD];
__device__ float    g_Rp [4 * LLEN * DD];
__device__ float    g_o1 [LLEN * DD];
__device__ unsigned g_ah [512 * DD];
__device__ unsigned g_am [512 * DD];
__device__ unsigned g_bh [512 * DD];
__device__ unsigned g_bm [512 * DD];
__device__ unsigned g_mkp[LLEN * 512];
__device__ unsigned g_tile_ctr;

// ---------------- helpers ----------------
__device__ __forceinline__ unsigned smem_u32(const void* p) {
    unsigned a;
    asm("{ .reg .u64 t; cvta.to.shared.u64 t, %1; cvt.u32.u64 %0, t; }" : "=r"(a) : "l"(p));
    return a;
}
// L1-ALLOCATING async copy (.ca): operands stay L1-resident across tiles.
#define CP_ASYNC16(dst, src) \
    asm volatile("cp.async.ca.shared.global [%0], [%1], 16;" :: "r"(dst), "l"(src))
#define CP_COMMIT() asm volatile("cp.async.commit_group;" ::: "memory")
#define CP_WAIT0()  asm volatile("cp.async.wait_group 0;" ::: "memory")

__device__ __forceinline__ unsigned pack_bf16x2(float lo, float hi) {
    unsigned u;
    asm("cvt.rn.bf16x2.f32 %0, %1, %2;" : "=r"(u) : "f"(hi), "f"(lo));
    return u;
}
__device__ __forceinline__ void split_bf16(float x0, float x1, unsigned& uh, unsigned& um) {
    uh = pack_bf16x2(x0, x1);
    float h0 = __uint_as_float(uh << 16);
    float h1 = __uint_as_float(uh & 0xFFFF0000u);
    um = pack_bf16x2(x0 - h0, x1 - h1);
}
__device__ __forceinline__ void mma_bf16(float* c, unsigned a0, unsigned a1, unsigned a2,
                                         unsigned a3, unsigned b0, unsigned b1) {
    asm volatile(
        "mma.sync.aligned.m16n8k16.row.col.f32.bf16.bf16.f32 "
        "{%0,%1,%2,%3}, {%4,%5,%6,%7}, {%8,%9}, {%0,%1,%2,%3};"
        : "+f"(c[0]), "+f"(c[1]), "+f"(c[2]), "+f"(c[3])
        : "r"(a0), "r"(a1), "r"(a2), "r"(a3), "r"(b0), "r"(b1));
}

// ---------------- kernel 1: projections + fused bf16 split ----------------
__global__ __launch_bounds__(256) void proj_kernel(
    const float* __restrict__ x,
    const float* __restrict__ Wl,  const float* __restrict__ bl,
    const float* __restrict__ Wl2, const float* __restrict__ bl2)
{
    __shared__ float xs[8 * DD];
    __shared__ float ws[32 * 129];
    __shared__ float ys[8 * DD];
    const int t = threadIdx.x, l0 = blockIdx.x * 8;
    const int dloc = t & 31, lrow = t >> 5;
    for (int i = t; i < 8 * DD; i += 256) xs[i] = x[l0 * DD + i];
    for (int mat = 0; mat < 2; mat++) {
        const float* W    = mat ? Wl2 : Wl;
        const float* bias = mat ? bl2 : bl;
        float*       outp = mat ? g_tx : g_a;
        unsigned*    oh   = mat ? g_bh : g_ah;
        unsigned*    om   = mat ? g_bm : g_am;
        for (int dc = 0; dc < 4; dc++) {
            const int d0 = dc * 32;
            __syncthreads();
            for (int i = t; i < 32 * DD; i += 256) {
                int r = i >> 7, c = i & 127;
                ws[r * 129 + c] = W[(d0 + r) * DD + c];
            }
            __syncthreads();
            float acc = 0.f;
            #pragma unroll 8
            for (int c = 0; c < DD; c++) acc += xs[lrow * DD + c] * ws[dloc * 129 + c];
            acc += bias[d0 + dloc];
            outp[(l0 + lrow) * DD + d0 + dloc] = acc;
            ys[lrow * DD + d0 + dloc] = acc;
        }
        __syncthreads();
        #pragma unroll
        for (int i = 0; i < 2; i++) {
            int idx = t + 256 * i;
            int j = idx >> 7, c = idx & 127;
            float x0 = ys[(2 * j) * DD + c];
            float x1 = ys[(2 * j + 1) * DD + c];
            unsigned uh, um; split_bf16(x0, x1, uh, um);
            int kp = (l0 >> 1) + j;
            oh[kp * DD + c] = uh; om[kp * DD + c] = um;
        }
    }
}

// ---------------- kernel 2: R partials + mask pair-words + ctr reset ----------------
__global__ __launch_bounds__(256) void r_kernel(const int* __restrict__ mask)
{
    __shared__ float s_txc[64 * DD];
    __shared__ float s_mk [16 * 64];
    const int t = threadIdx.x;
    const int l0 = blockIdx.x * 16;
    const int mg = blockIdx.y;
    const int d4 = t & 31, lg = t >> 5;
    if (blockIdx.x == 0 && mg == 0 && t == 0) g_tile_ctr = 0u;

    #pragma unroll
    for (int i = 0; i < 8; i++) {
        int idx = t + 256 * i;                // 0..2047
        int li = idx >> 7, kpl = idx & 127;
        int kp = mg * 128 + kpl;
        int ma = mask[(l0 + li) * LLEN + 2 * kp];
        int mb = mask[(l0 + li) * LLEN + 2 * kp + 1];
        g_mkp[(l0 + li) * 512 + kp] = (ma ? 0x0000FFFFu : 0u) | (mb ? 0xFFFF0000u : 0u);
    }

    float4 a0 = {0.f,0.f,0.f,0.f}, a1 = {0.f,0.f,0.f,0.f};
    for (int ch = 0; ch < 4; ch++) {
        const int m0 = mg * 256 + ch * 64;
        __syncthreads();
        #pragma unroll
        for (int r = 0; r < 8; r++) {
            int idx = t + 256 * r;
            int rw = idx >> 5, c4 = idx & 31;
            *(float4*)&s_txc[rw * DD + c4 * 4] = *(const float4*)&g_tx[(m0 + rw) * DD + c4 * 4];
        }
        #pragma unroll
        for (int r = 0; r < 4; r++) {
            int idx = t + 256 * r;
            int li = idx >> 6, mm = idx & 63;
            s_mk[li * 64 + mm] = (mask[(l0 + li) * LLEN + m0 + mm] != 0) ? 1.f : 0.f;
        }
        __syncthreads();
        #pragma unroll 4
        for (int mm = 0; mm < 64; mm++) {
            float4 tv = *(float4*)&s_txc[mm * DD + d4 * 4];
            float f0 = s_mk[(lg * 2) * 64 + mm];
            float f1 = s_mk[(lg * 2 + 1) * 64 + mm];
            a0.x += tv.x * f0; a0.y += tv.y * f0; a0.z += tv.z * f0; a0.w += tv.w * f0;
            a1.x += tv.x * f1; a1.y += tv.y * f1; a1.z += tv.z * f1; a1.w += tv.w * f1;
        }
    }
    *(float4*)&g_Rp[(mg * LLEN + l0 + lg * 2) * DD + d4 * 4]     = a0;
    *(float4*)&g_Rp[(mg * LLEN + l0 + lg * 2 + 1) * DD + d4 * 4] = a1;
}

// ---------------- kernel 3: persistent mma.sync GEMM, cp.async.ca double-buffer, KC=64 ----------------
// SMEM: s_a 0..2048, s_mk 2048..10240,
//   buf0 @10240, buf1 @63488; each: Ah(17408) Am(17408) Bh(9216) Bm(9216) = 53248
// Epilogue reuse: wlo@10240 (33792), ep@44032 (8192). Total dynamic = 116736.
__global__ __launch_bounds__(256, 1) void cop_kernel(const float* __restrict__ Wlo)
{
    extern __shared__ char sm[];
    float*    s_a   = (float*)sm;
    unsigned* s_mk  = (unsigned*)(sm + 2048);
    float*    s_wlo = (float*)(sm + 10240);
    float*    s_ep  = (float*)(sm + 44032);
    __shared__ int s_tile;
    const unsigned sb = smem_u32(sm);

    const int t    = threadIdx.x;
    const int w    = t >> 5;
    const int lane = t & 31;
    const int gid  = lane >> 2;
    const int tig  = lane & 3;
    const int ct0  = w * 16;

    for (;;) {
        if (t == 0) s_tile = (int)atomicAdd(&g_tile_ctr, 1u);
        __syncthreads();
        const int tile = s_tile;
        if (tile >= NTILE) break;
        const int l0 = (tile >> 1) * LP;
        const int d0 = (tile & 1) * 64;

        #pragma unroll
        for (int i = 0; i < 2; i++) {
            int idx = t + 256 * i;
            s_a[idx] = g_a[(l0 + (idx >> 7)) * DD + (idx & 127)];
        }
        #pragma unroll
        for (int i = 0; i < 8; i++) {
            int idx = t + 256 * i;
            s_mk[idx] = g_mkp[(l0 + (idx >> 9)) * 512 + (idx & 511)];
        }

        float acc[LP][8][4];
        #pragma unroll
        for (int l = 0; l < LP; l++)
            #pragma unroll
            for (int dg = 0; dg < 8; dg++)
                #pragma unroll
                for (int q = 0; q < 4; q++) acc[l][dg][q] = 0.f;

        // ---- issue round-0 copies ----
        {
            const unsigned bufu = sb + 10240;
            #pragma unroll
            for (int i = 0; i < 4; i++) {
                int idx = t + 256 * i;
                int rw = idx >> 5, c4 = idx & 31;
                const unsigned dsto = rw * 136 + c4 * 4;
                CP_ASYNC16(bufu + dsto * 4,         (const char*)(g_ah + rw * 128 + c4 * 4));
                CP_ASYNC16(bufu + 17408 + dsto * 4, (const char*)(g_am + rw * 128 + c4 * 4));
            }
            #pragma unroll
            for (int i = 0; i < 2; i++) {
                int idx = t + 256 * i;
                int rw = idx >> 4, c4 = idx & 15;
                const unsigned dsto = rw * 72 + c4 * 4;
                CP_ASYNC16(bufu + 34816 + dsto * 4, (const char*)(g_bh + rw * 128 + d0 + c4 * 4));
                CP_ASYNC16(bufu + 44032 + dsto * 4, (const char*)(g_bm + rw * 128 + d0 + c4 * 4));
            }
            CP_COMMIT();
        }

        #pragma unroll 1
        for (int r = 0; r < 16; r++) {
            CP_WAIT0();          // round-r copies landed (this thread)
            __syncthreads();     // everyone's landed; prev round's reads done
            if (r < 15) {        // issue round r+1 into the other buffer
                const int kg = (r + 1) * 32;
                const unsigned bufu = sb + 10240 + ((r + 1) & 1) * BUFB;
                #pragma unroll
                for (int i = 0; i < 4; i++) {
                    int idx = t + 256 * i;
                    int rw = idx >> 5, c4 = idx & 31;
                    const unsigned dsto = rw * 136 + c4 * 4;
                    const unsigned srco = (kg + rw) * 128 + c4 * 4;
                    CP_ASYNC16(bufu + dsto * 4,         (const char*)(g_ah + srco));
                    CP_ASYNC16(bufu + 17408 + dsto * 4, (const char*)(g_am + srco));
                }
                #pragma unroll
                for (int i = 0; i < 2; i++) {
                    int idx = t + 256 * i;
                    int rw = idx >> 4, c4 = idx & 15;
                    const unsigned dsto = rw * 72 + c4 * 4;
                    const unsigned srco = (kg + rw) * 128 + d0 + c4 * 4;
                    CP_ASYNC16(bufu + 34816 + dsto * 4, (const char*)(g_bh + srco));
                    CP_ASYNC16(bufu + 44032 + dsto * 4, (const char*)(g_bm + srco));
                }
                CP_COMMIT();
            }
            char* buf = sm + 10240 + (r & 1) * BUFB;
            unsigned* sAh = (unsigned*)(buf);
            unsigned* sAm = (unsigned*)(buf + 17408);
            unsigned* sBh = (unsigned*)(buf + 34816);
            unsigned* sBm = (unsigned*)(buf + 44032);
            const int kpg = r * 32;
            #pragma unroll
            for (int s = 0; s < 4; s++) {
                const int kb = 8 * s;
                unsigned ah0 = sAh[(kb + tig) * 136 + ct0 + gid];
                unsigned ah1 = sAh[(kb + tig) * 136 + ct0 + gid + 8];
                unsigned ah2 = sAh[(kb + tig + 4) * 136 + ct0 + gid];
                unsigned ah3 = sAh[(kb + tig + 4) * 136 + ct0 + gid + 8];
                unsigned am0 = sAm[(kb + tig) * 136 + ct0 + gid];
                unsigned am1 = sAm[(kb + tig) * 136 + ct0 + gid + 8];
                unsigned am2 = sAm[(kb + tig + 4) * 136 + ct0 + gid];
                unsigned am3 = sAm[(kb + tig + 4) * 136 + ct0 + gid + 8];
                unsigned mkl[LP], mkh[LP];
                #pragma unroll
                for (int l = 0; l < LP; l++) {
                    mkl[l] = s_mk[l * 512 + kpg + kb + tig];
                    mkh[l] = s_mk[l * 512 + kpg + kb + tig + 4];
                }
                unsigned b0[8], b1[8];
                #pragma unroll
                for (int dg = 0; dg < 8; dg++) {
                    b0[dg] = sBh[(kb + tig) * 72 + dg * 8 + gid];
                    b1[dg] = sBh[(kb + tig + 4) * 72 + dg * 8 + gid];
                }
                #pragma unroll
                for (int l = 0; l < LP; l++) {      // hh
                    unsigned x0 = ah0 & mkl[l], x1 = ah1 & mkl[l];
                    unsigned x2 = ah2 & mkh[l], x3 = ah3 & mkh[l];
                    #pragma unroll
                    for (int dg = 0; dg < 8; dg++)
                        mma_bf16(acc[l][dg], x0, x1, x2, x3, b0[dg], b1[dg]);
                }
                #pragma unroll
                for (int l = 0; l < LP; l++) {      // mh
                    unsigned x0 = am0 & mkl[l], x1 = am1 & mkl[l];
                    unsigned x2 = am2 & mkh[l], x3 = am3 & mkh[l];
                    #pragma unroll
                    for (int dg = 0; dg < 8; dg++)
                        mma_bf16(acc[l][dg], x0, x1, x2, x3, b0[dg], b1[dg]);
                }
                #pragma unroll
                for (int dg = 0; dg < 8; dg++) {
                    b0[dg] = sBm[(kb + tig) * 72 + dg * 8 + gid];
                    b1[dg] = sBm[(kb + tig + 4) * 72 + dg * 8 + gid];
                }
                #pragma unroll
                for (int l = 0; l < LP; l++) {      // hm
                    unsigned x0 = ah0 & mkl[l], x1 = ah1 & mkl[l];
                    unsigned x2 = ah2 & mkh[l], x3 = ah3 & mkh[l];
                    #pragma unroll
                    for (int dg = 0; dg < 8; dg++)
                        mma_bf16(acc[l][dg], x0, x1, x2, x3, b0[dg], b1[dg]);
                }
            }
        }

        // ---- epilogue: sum_c a_l[c]*Wlo[d,c]*H ----
        __syncthreads();
        #pragma unroll
        for (int i = 0; i < 8; i++) {
            int idx = t + 256 * i;              // 2048 float4s = 64 d x 32 c4
            int dd = idx >> 5, c4 = idx & 31;
            *(float4*)&s_wlo[dd * 132 + c4 * 4] = *(const float4*)&Wlo[(d0 + dd) * DD + c4 * 4];
        }
        __syncthreads();

        const int cA = ct0 + gid, cB = cA + 8;
        #pragma unroll
        for (int l = 0; l < LP; l++) {
            const float aA = s_a[l * DD + cA];
            const float aB = s_a[l * DD + cB];
            float pd[16];
            #pragma unroll
            for (int dg = 0; dg < 8; dg++) {
                const int dl0 = dg * 8 + 2 * tig;
                float w0  = s_wlo[dl0 * 132 + cA],  w1  = s_wlo[(dl0 + 1) * 132 + cA];
                float w0b = s_wlo[dl0 * 132 + cB],  w1b = s_wlo[(dl0 + 1) * 132 + cB];
                pd[2 * dg]     = acc[l][dg][0] * (aA * w0) + acc[l][dg][2] * (aB * w0b);
                pd[2 * dg + 1] = acc[l][dg][1] * (aA * w1) + acc[l][dg][3] * (aB * w1b);
            }
            #pragma unroll
            for (int off = 16; off >= 4; off >>= 1)
                #pragma unroll
                for (int q = 0; q < 16; q++)
                    pd[q] += __shfl_down_sync(0xffffffffu, pd[q], off);
            if (lane < 4) {
                #pragma unroll
                for (int dg = 0; dg < 8; dg++) {
                    s_ep[w * 256 + l * 64 + dg * 8 + 2 * lane]     = pd[2 * dg];
                    s_ep[w * 256 + l * 64 + dg * 8 + 2 * lane + 1] = pd[2 * dg + 1];
                }
            }
        }
        __syncthreads();
        {
            const int l = t >> 6, dloc = t & 63;
            float v = s_ep[t] + s_ep[256 + t] + s_ep[512 + t] + s_ep[768 + t]
                    + s_ep[1024 + t] + s_ep[1280 + t] + s_ep[1536 + t] + s_ep[1792 + t];
            g_o1[(l0 + l) * DD + d0 + dloc] = v;
        }
    }
}

// ---------------- kernel 4: residual + blo*R + LayerNorm ----------------
__global__ __launch_bounds__(128) void ln_kernel(
    const float* __restrict__ x,   const float* __restrict__ blo,
    const float* __restrict__ gamma, const float* __restrict__ beta,
    float* __restrict__ out)
{
    __shared__ float w1[4], w2[4];
    __shared__ float mu_s, rstd_s;
    const int l = blockIdx.x;
    const int d = threadIdx.x;
    float Rv = g_Rp[l * DD + d] + g_Rp[(LLEN + l) * DD + d]
             + g_Rp[(2 * LLEN + l) * DD + d] + g_Rp[(3 * LLEN + l) * DD + d];
    float y = x[l * DD + d] + g_o1[l * DD + d] + blo[d] * Rv;
    float s1 = y, s2 = y * y;
    #pragma unroll
    for (int off = 16; off > 0; off >>= 1) {
        s1 += __shfl_down_sync(0xffffffffu, s1, off);
        s2 += __shfl_down_sync(0xffffffffu, s2, off);
    }
    const int wid = d >> 5, lid = d & 31;
    if (lid == 0) { w1[wid] = s1; w2[wid] = s2; }
    __syncthreads();
    if (d == 0) {
        float t1 = w1[0] + w1[1] + w1[2] + w1[3];
        float t2 = w2[0] + w2[1] + w2[2] + w2[3];
        float mu = t1 * (1.f / DD);
        float var = t2 * (1.f / DD) - mu * mu;
        mu_s = mu; rstd_s = rsqrtf(var + EPSF);
    }
    __syncthreads();
    out[l * DD + d] = (y - mu_s) * rstd_s * gamma[d] + beta[d];
}

// ---------------- launch ----------------
extern "C" void kernel_launch(void* const* d_in, const int* in_sizes, int n_in,
                              void* d_out, int out_size)
{
    (void)in_sizes; (void)n_in; (void)out_size;
    const float* x     = (const float*)d_in[0];
    const int*   mask  = (const int*)  d_in[1];
    const float* Wl    = (const float*)d_in[2];
    const float* bl    = (const float*)d_in[3];
    const float* Wlo   = (const float*)d_in[4];
    const float* blo   = (const float*)d_in[5];
    const float* Wl2   = (const float*)d_in[6];
    const float* bl2   = (const float*)d_in[7];
    const float* gamma = (const float*)d_in[8];
    const float* beta  = (const float*)d_in[9];
    float* out = (float*)d_out;

    static int smem_set = 0;
    if (!smem_set) {
        cudaFuncSetAttribute(cop_kernel, cudaFuncAttributeMaxDynamicSharedMemorySize, 116736);
        smem_set = 1;
    }

    proj_kernel<<<128, 256>>>(x, Wl, bl, Wl2, bl2);        // 1
    r_kernel<<<dim3(64, 4), 256>>>(mask);                  // 2
    cop_kernel<<<148, 256, 116736>>>(Wlo);                 // 3
    ln_kernel<<<1024, 128>>>(x, blo, gamma, beta, out);    // 4
}

// round 10
// speedup vs baseline: 1.1735x; 1.0816x over previous
#include <cuda_runtime.h>
#include <cuda_bf16.h>

#define LLEN 1024
#define DD   128
#define EPSF 1e-5f
#define LP   2
#define NTILE 1024    // 512 l-tiles (2 l each) x 2 d-halves
#define BUFB 26624    // bytes per round buffer: Ah 8704 + Am 8704 + Bh 4608 + Bm 4608

// ---------------- scratch (device globals; no allocation) ----------------
__device__ float    g_a  [LLEN * DD];
__device__ float    g_tx [LLEN * DD];
__device__ float    g_Rp [4 * LLEN * DD];
__device__ float    g_o1 [LLEN * DD];
__device__ unsigned g_ah [512 * DD];
__device__ unsigned g_am [512 * DD];
__device__ unsigned g_bh [512 * DD];
__device__ unsigned g_bm [512 * DD];
__device__ unsigned g_mkp[LLEN * 512];
__device__ unsigned g_tile_ctr;

// ---------------- helpers ----------------
__device__ __forceinline__ unsigned smem_u32(const void* p) {
    unsigned a;
    asm("{ .reg .u64 t; cvta.to.shared.u64 t, %1; cvt.u32.u64 %0, t; }" : "=r"(a) : "l"(p));
    return a;
}
// L1-allocating async copy: operands stay L1-resident across tiles.
#define CP_ASYNC16(dst, src) \
    asm volatile("cp.async.ca.shared.global [%0], [%1], 16;" :: "r"(dst), "l"(src))
#define CP_COMMIT() asm volatile("cp.async.commit_group;" ::: "memory")
#define CP_WAIT0()  asm volatile("cp.async.wait_group 0;" ::: "memory")

__device__ __forceinline__ unsigned pack_bf16x2(float lo, float hi) {
    unsigned u;
    asm("cvt.rn.bf16x2.f32 %0, %1, %2;" : "=r"(u) : "f"(hi), "f"(lo));
    return u;
}
__device__ __forceinline__ void split_bf16(float x0, float x1, unsigned& uh, unsigned& um) {
    uh = pack_bf16x2(x0, x1);
    float h0 = __uint_as_float(uh << 16);
    float h1 = __uint_as_float(uh & 0xFFFF0000u);
    um = pack_bf16x2(x0 - h0, x1 - h1);
}
__device__ __forceinline__ void mma_bf16(float* c, unsigned a0, unsigned a1, unsigned a2,
                                         unsigned a3, unsigned b0, unsigned b1) {
    asm volatile(
        "mma.sync.aligned.m16n8k16.row.col.f32.bf16.bf16.f32 "
        "{%0,%1,%2,%3}, {%4,%5,%6,%7}, {%8,%9}, {%0,%1,%2,%3};"
        : "+f"(c[0]), "+f"(c[1]), "+f"(c[2]), "+f"(c[3])
        : "r"(a0), "r"(a1), "r"(a2), "r"(a3), "r"(b0), "r"(b1));
}

// ---------------- kernel 1: projections + fused bf16 split ----------------
__global__ __launch_bounds__(256) void proj_kernel(
    const float* __restrict__ x,
    const float* __restrict__ Wl,  const float* __restrict__ bl,
    const float* __restrict__ Wl2, const float* __restrict__ bl2)
{
    __shared__ float xs[8 * DD];
    __shared__ float ws[32 * 129];
    __shared__ float ys[8 * DD];
    const int t = threadIdx.x, l0 = blockIdx.x * 8;
    const int dloc = t & 31, lrow = t >> 5;
    for (int i = t; i < 8 * DD; i += 256) xs[i] = x[l0 * DD + i];
    for (int mat = 0; mat < 2; mat++) {
        const float* W    = mat ? Wl2 : Wl;
        const float* bias = mat ? bl2 : bl;
        float*       outp = mat ? g_tx : g_a;
        unsigned*    oh   = mat ? g_bh : g_ah;
        unsigned*    om   = mat ? g_bm : g_am;
        for (int dc = 0; dc < 4; dc++) {
            const int d0 = dc * 32;
            __syncthreads();
            for (int i = t; i < 32 * DD; i += 256) {
                int r = i >> 7, c = i & 127;
                ws[r * 129 + c] = W[(d0 + r) * DD + c];
            }
            __syncthreads();
            float acc = 0.f;
            #pragma unroll 8
            for (int c = 0; c < DD; c++) acc += xs[lrow * DD + c] * ws[dloc * 129 + c];
            acc += bias[d0 + dloc];
            outp[(l0 + lrow) * DD + d0 + dloc] = acc;
            ys[lrow * DD + d0 + dloc] = acc;
        }
        __syncthreads();
        #pragma unroll
        for (int i = 0; i < 2; i++) {
            int idx = t + 256 * i;
            int j = idx >> 7, c = idx & 127;
            float x0 = ys[(2 * j) * DD + c];
            float x1 = ys[(2 * j + 1) * DD + c];
            unsigned uh, um; split_bf16(x0, x1, uh, um);
            int kp = (l0 >> 1) + j;
            oh[kp * DD + c] = uh; om[kp * DD + c] = um;
        }
    }
}

// ---------------- kernel 2: R partials + mask pair-words + ctr reset ----------------
__global__ __launch_bounds__(256) void r_kernel(const int* __restrict__ mask)
{
    __shared__ float s_txc[64 * DD];
    __shared__ float s_mk [16 * 64];
    const int t = threadIdx.x;
    const int l0 = blockIdx.x * 16;
    const int mg = blockIdx.y;
    const int d4 = t & 31, lg = t >> 5;
    if (blockIdx.x == 0 && mg == 0 && t == 0) g_tile_ctr = 0u;

    #pragma unroll
    for (int i = 0; i < 8; i++) {
        int idx = t + 256 * i;
        int li = idx >> 7, kpl = idx & 127;
        int kp = mg * 128 + kpl;
        int ma = mask[(l0 + li) * LLEN + 2 * kp];
        int mb = mask[(l0 + li) * LLEN + 2 * kp + 1];
        g_mkp[(l0 + li) * 512 + kp] = (ma ? 0x0000FFFFu : 0u) | (mb ? 0xFFFF0000u : 0u);
    }

    float4 a0 = {0.f,0.f,0.f,0.f}, a1 = {0.f,0.f,0.f,0.f};
    for (int ch = 0; ch < 4; ch++) {
        const int m0 = mg * 256 + ch * 64;
        __syncthreads();
        #pragma unroll
        for (int r = 0; r < 8; r++) {
            int idx = t + 256 * r;
            int rw = idx >> 5, c4 = idx & 31;
            *(float4*)&s_txc[rw * DD + c4 * 4] = *(const float4*)&g_tx[(m0 + rw) * DD + c4 * 4];
        }
        #pragma unroll
        for (int r = 0; r < 4; r++) {
            int idx = t + 256 * r;
            int li = idx >> 6, mm = idx & 63;
            s_mk[li * 64 + mm] = (mask[(l0 + li) * LLEN + m0 + mm] != 0) ? 1.f : 0.f;
        }
        __syncthreads();
        #pragma unroll 4
        for (int mm = 0; mm < 64; mm++) {
            float4 tv = *(float4*)&s_txc[mm * DD + d4 * 4];
            float f0 = s_mk[(lg * 2) * 64 + mm];
            float f1 = s_mk[(lg * 2 + 1) * 64 + mm];
            a0.x += tv.x * f0; a0.y += tv.y * f0; a0.z += tv.z * f0; a0.w += tv.w * f0;
            a1.x += tv.x * f1; a1.y += tv.y * f1; a1.z += tv.z * f1; a1.w += tv.w * f1;
        }
    }
    *(float4*)&g_Rp[(mg * LLEN + l0 + lg * 2) * DD + d4 * 4]     = a0;
    *(float4*)&g_Rp[(mg * LLEN + l0 + lg * 2 + 1) * DD + d4 * 4] = a1;
}

// ---------------- kernel 3: persistent GEMM, 2 CTAs/SM, LP=2, KC=32, cp.async.ca ----------------
// SMEM/CTA: s_a @0 (1024), s_mk @1024 (4096),
//   buf0 @5120, buf1 @31744; each: Ah(8704) Am(8704) Bh(4608) Bm(4608) = 26624 -> end 58368
// Epilogue reuse: wlo @5120 (33792), ep @38912 (4096). Dynamic = 58368.
__global__ __launch_bounds__(256, 2) void cop_kernel(const float* __restrict__ Wlo)
{
    extern __shared__ char sm[];
    float*    s_a   = (float*)sm;
    unsigned* s_mk  = (unsigned*)(sm + 1024);
    float*    s_wlo = (float*)(sm + 5120);
    float*    s_ep  = (float*)(sm + 38912);
    __shared__ int s_tile;
    const unsigned sb = smem_u32(sm);

    const int t    = threadIdx.x;
    const int w    = t >> 5;
    const int lane = t & 31;
    const int gid  = lane >> 2;
    const int tig  = lane & 3;
    const int ct0  = w * 16;

    for (;;) {
        if (t == 0) s_tile = (int)atomicAdd(&g_tile_ctr, 1u);
        __syncthreads();
        const int tile = s_tile;
        if (tile >= NTILE) break;
        const int l0 = (tile >> 1) * LP;
        const int d0 = (tile & 1) * 64;

        // stage a_l + mask pair-words
        if (t < LP * DD) s_a[t] = g_a[(l0 + (t >> 7)) * DD + (t & 127)];
        #pragma unroll
        for (int i = 0; i < 4; i++) {
            int idx = t + 256 * i;               // 0..1023
            s_mk[idx] = g_mkp[(l0 + (idx >> 9)) * 512 + (idx & 511)];
        }

        float acc[LP][8][4];
        #pragma unroll
        for (int l = 0; l < LP; l++)
            #pragma unroll
            for (int dg = 0; dg < 8; dg++)
                #pragma unroll
                for (int q = 0; q < 4; q++) acc[l][dg][q] = 0.f;

        // ---- issue round-0 copies (16 kp rows) ----
        {
            const unsigned bufu = sb + 5120;
            #pragma unroll
            for (int i = 0; i < 2; i++) {
                int idx = t + 256 * i;           // 0..511
                int rw = idx >> 5, c4 = idx & 31;
                const unsigned dsto = (rw * 136 + c4 * 4) * 4;
                CP_ASYNC16(bufu + dsto,        (const char*)(g_ah + rw * 128 + c4 * 4));
                CP_ASYNC16(bufu + 8704 + dsto, (const char*)(g_am + rw * 128 + c4 * 4));
            }
            {
                int rw = t >> 4, c4 = t & 15;    // 256 threads = 16x16
                const unsigned dsto = (rw * 72 + c4 * 4) * 4;
                CP_ASYNC16(bufu + 17408 + dsto, (const char*)(g_bh + rw * 128 + d0 + c4 * 4));
                CP_ASYNC16(bufu + 22016 + dsto, (const char*)(g_bm + rw * 128 + d0 + c4 * 4));
            }
            CP_COMMIT();
        }

        #pragma unroll 1
        for (int r = 0; r < 32; r++) {
            CP_WAIT0();
            __syncthreads();
            if (r < 31) {
                const int kg = (r + 1) * 16;
                const unsigned bufu = sb + 5120 + ((r + 1) & 1) * BUFB;
                #pragma unroll
                for (int i = 0; i < 2; i++) {
                    int idx = t + 256 * i;
                    int rw = idx >> 5, c4 = idx & 31;
                    const unsigned dsto = (rw * 136 + c4 * 4) * 4;
                    const unsigned srco = (kg + rw) * 128 + c4 * 4;
                    CP_ASYNC16(bufu + dsto,        (const char*)(g_ah + srco));
                    CP_ASYNC16(bufu + 8704 + dsto, (const char*)(g_am + srco));
                }
                {
                    int rw = t >> 4, c4 = t & 15;
                    const unsigned dsto = (rw * 72 + c4 * 4) * 4;
                    const unsigned srco = (kg + rw) * 128 + d0 + c4 * 4;
                    CP_ASYNC16(bufu + 17408 + dsto, (const char*)(g_bh + srco));
                    CP_ASYNC16(bufu + 22016 + dsto, (const char*)(g_bm + srco));
                }
                CP_COMMIT();
            }
            char* buf = sm + 5120 + (r & 1) * BUFB;
            unsigned* sAh = (unsigned*)(buf);
            unsigned* sAm = (unsigned*)(buf + 8704);
            unsigned* sBh = (unsigned*)(buf + 17408);
            unsigned* sBm = (unsigned*)(buf + 22016);
            const int kpg = r * 16;
            #pragma unroll
            for (int s = 0; s < 2; s++) {
                const int kb = 8 * s;
                unsigned ah0 = sAh[(kb + tig) * 136 + ct0 + gid];
                unsigned ah1 = sAh[(kb + tig) * 136 + ct0 + gid + 8];
                unsigned ah2 = sAh[(kb + tig + 4) * 136 + ct0 + gid];
                unsigned ah3 = sAh[(kb + tig + 4) * 136 + ct0 + gid + 8];
                unsigned am0 = sAm[(kb + tig) * 136 + ct0 + gid];
                unsigned am1 = sAm[(kb + tig) * 136 + ct0 + gid + 8];
                unsigned am2 = sAm[(kb + tig + 4) * 136 + ct0 + gid];
                unsigned am3 = sAm[(kb + tig + 4) * 136 + ct0 + gid + 8];
                unsigned mkl[LP], mkh[LP];
                #pragma unroll
                for (int l = 0; l < LP; l++) {
                    mkl[l] = s_mk[l * 512 + kpg + kb + tig];
                    mkh[l] = s_mk[l * 512 + kpg + kb + tig + 4];
                }
                unsigned b0[8], b1[8];
                #pragma unroll
                for (int dg = 0; dg < 8; dg++) {
                    b0[dg] = sBh[(kb + tig) * 72 + dg * 8 + gid];
                    b1[dg] = sBh[(kb + tig + 4) * 72 + dg * 8 + gid];
                }
                #pragma unroll
                for (int l = 0; l < LP; l++) {      // hh
                    unsigned x0 = ah0 & mkl[l], x1 = ah1 & mkl[l];
                    unsigned x2 = ah2 & mkh[l], x3 = ah3 & mkh[l];
                    #pragma unroll
                    for (int dg = 0; dg < 8; dg++)
                        mma_bf16(acc[l][dg], x0, x1, x2, x3, b0[dg], b1[dg]);
                }
                #pragma unroll
                for (int l = 0; l < LP; l++) {      // mh
                    unsigned x0 = am0 & mkl[l], x1 = am1 & mkl[l];
                    unsigned x2 = am2 & mkh[l], x3 = am3 & mkh[l];
                    #pragma unroll
                    for (int dg = 0; dg < 8; dg++)
                        mma_bf16(acc[l][dg], x0, x1, x2, x3, b0[dg], b1[dg]);
                }
                #pragma unroll
                for (int dg = 0; dg < 8; dg++) {
                    b0[dg] = sBm[(kb + tig) * 72 + dg * 8 + gid];
                    b1[dg] = sBm[(kb + tig + 4) * 72 + dg * 8 + gid];
                }
                #pragma unroll
                for (int l = 0; l < LP; l++) {      // hm
                    unsigned x0 = ah0 & mkl[l], x1 = ah1 & mkl[l];
                    unsigned x2 = ah2 & mkh[l], x3 = ah3 & mkh[l];
                    #pragma unroll
                    for (int dg = 0; dg < 8; dg++)
                        mma_bf16(acc[l][dg], x0, x1, x2, x3, b0[dg], b1[dg]);
                }
            }
        }

        // ---- epilogue: sum_c a_l[c]*Wlo[d,c]*H ----
        __syncthreads();
        #pragma unroll
        for (int i = 0; i < 8; i++) {
            int idx = t + 256 * i;              // 2048 float4s = 64 d x 32 c4
            int dd = idx >> 5, c4 = idx & 31;
            *(float4*)&s_wlo[dd * 132 + c4 * 4] = *(const float4*)&Wlo[(d0 + dd) * DD + c4 * 4];
        }
        __syncthreads();

        const int cA = ct0 + gid, cB = cA + 8;
        #pragma unroll
        for (int l = 0; l < LP; l++) {
            const float aA = s_a[l * DD + cA];
            const float aB = s_a[l * DD + cB];
            float pd[16];
            #pragma unroll
            for (int dg = 0; dg < 8; dg++) {
                const int dl0 = dg * 8 + 2 * tig;
                float w0  = s_wlo[dl0 * 132 + cA],  w1  = s_wlo[(dl0 + 1) * 132 + cA];
                float w0b = s_wlo[dl0 * 132 + cB],  w1b = s_wlo[(dl0 + 1) * 132 + cB];
                pd[2 * dg]     = acc[l][dg][0] * (aA * w0) + acc[l][dg][2] * (aB * w0b);
                pd[2 * dg + 1] = acc[l][dg][1] * (aA * w1) + acc[l][dg][3] * (aB * w1b);
            }
            #pragma unroll
            for (int off = 16; off >= 4; off >>= 1)
                #pragma unroll
                for (int q = 0; q < 16; q++)
                    pd[q] += __shfl_down_sync(0xffffffffu, pd[q], off);
            if (lane < 4) {
                #pragma unroll
                for (int dg = 0; dg < 8; dg++) {
                    s_ep[w * 128 + l * 64 + dg * 8 + 2 * lane]     = pd[2 * dg];
                    s_ep[w * 128 + l * 64 + dg * 8 + 2 * lane + 1] = pd[2 * dg + 1];
                }
            }
        }
        __syncthreads();
        if (t < 128) {
            const int l = t >> 6, dloc = t & 63;
            float v = s_ep[t] + s_ep[128 + t] + s_ep[256 + t] + s_ep[384 + t]
                    + s_ep[512 + t] + s_ep[640 + t] + s_ep[768 + t] + s_ep[896 + t];
            g_o1[(l0 + l) * DD + d0 + dloc] = v;
        }
    }
}

// ---------------- kernel 4: residual + blo*R + LayerNorm ----------------
__global__ __launch_bounds__(128) void ln_kernel(
    const float* __restrict__ x,   const float* __restrict__ blo,
    const float* __restrict__ gamma, const float* __restrict__ beta,
    float* __restrict__ out)
{
    __shared__ float w1[4], w2[4];
    __shared__ float mu_s, rstd_s;
    const int l = blockIdx.x;
    const int d = threadIdx.x;
    float Rv = g_Rp[l * DD + d] + g_Rp[(LLEN + l) * DD + d]
             + g_Rp[(2 * LLEN + l) * DD + d] + g_Rp[(3 * LLEN + l) * DD + d];
    float y = x[l * DD + d] + g_o1[l * DD + d] + blo[d] * Rv;
    float s1 = y, s2 = y * y;
    #pragma unroll
    for (int off = 16; off > 0; off >>= 1) {
        s1 += __shfl_down_sync(0xffffffffu, s1, off);
        s2 += __shfl_down_sync(0xffffffffu, s2, off);
    }
    const int wid = d >> 5, lid = d & 31;
    if (lid == 0) { w1[wid] = s1; w2[wid] = s2; }
    __syncthreads();
    if (d == 0) {
        float t1 = w1[0] + w1[1] + w1[2] + w1[3];
        float t2 = w2[0] + w2[1] + w2[2] + w2[3];
        float mu = t1 * (1.f / DD);
        float var = t2 * (1.f / DD) - mu * mu;
        mu_s = mu; rstd_s = rsqrtf(var + EPSF);
    }
    __syncthreads();
    out[l * DD + d] = (y - mu_s) * rstd_s * gamma[d] + beta[d];
}

// ---------------- launch ----------------
extern "C" void kernel_launch(void* const* d_in, const int* in_sizes, int n_in,
                              void* d_out, int out_size)
{
    (void)in_sizes; (void)n_in; (void)out_size;
    const float* x     = (const float*)d_in[0];
    const int*   mask  = (const int*)  d_in[1];
    const float* Wl    = (const float*)d_in[2];
    const float* bl    = (const float*)d_in[3];
    const float* Wlo   = (const float*)d_in[4];
    const float* blo   = (const float*)d_in[5];
    const float* Wl2   = (const float*)d_in[6];
    const float* bl2   = (const float*)d_in[7];
    const float* gamma = (const float*)d_in[8];
    const float* beta  = (const float*)d_in[9];
    float* out = (float*)d_out;

    static int smem_set = 0;
    if (!smem_set) {
        cudaFuncSetAttribute(cop_kernel, cudaFuncAttributeMaxDynamicSharedMemorySize, 58368);
        smem_set = 1;
    }

    proj_kernel<<<128, 256>>>(x, Wl, bl, Wl2, bl2);        // 1
    r_kernel<<<dim3(64, 4), 256>>>(mask);                  // 2
    cop_kernel<<<296, 256, 58368>>>(Wlo);                  // 3
    ln_kernel<<<1024, 128>>>(x, blo, gamma, beta, out);    // 4
}

// round 11
// speedup vs baseline: 1.1994x; 1.0221x over previous
#include <cuda_runtime.h>
#include <cuda_bf16.h>

#define LLEN 1024
#define DD   128
#define EPSF 1e-5f
#define LP   2
#define NTILE 1024    // 512 l-tiles (2 l each) x 2 d-halves
#define BUFB 26624    // bytes per round buffer: Ah 8704 + Am 8704 + Bh 4608 + Bm 4608
#define NRP  16       // R partials (m-groups of 64)

// ---------------- scratch (device globals; no allocation) ----------------
__device__ float    g_a  [LLEN * DD];
__device__ float    g_tx [LLEN * DD];
__device__ float    g_Rp [NRP * LLEN * DD];
__device__ float    g_o1 [LLEN * DD];
__device__ unsigned g_ah [512 * DD];
__device__ unsigned g_am [512 * DD];
__device__ unsigned g_bh [512 * DD];
__device__ unsigned g_bm [512 * DD];
__device__ unsigned g_mkp[LLEN * 512];
__device__ unsigned g_tile_ctr;

// ---------------- helpers ----------------
__device__ __forceinline__ unsigned smem_u32(const void* p) {
    unsigned a;
    asm("{ .reg .u64 t; cvta.to.shared.u64 t, %1; cvt.u32.u64 %0, t; }" : "=r"(a) : "l"(p));
    return a;
}
// L1-allocating async copy: operands stay L1-resident across tiles.
#define CP_ASYNC16(dst, src) \
    asm volatile("cp.async.ca.shared.global [%0], [%1], 16;" :: "r"(dst), "l"(src))
#define CP_COMMIT() asm volatile("cp.async.commit_group;" ::: "memory")
#define CP_WAIT0()  asm volatile("cp.async.wait_group 0;" ::: "memory")

__device__ __forceinline__ unsigned pack_bf16x2(float lo, float hi) {
    unsigned u;
    asm("cvt.rn.bf16x2.f32 %0, %1, %2;" : "=r"(u) : "f"(hi), "f"(lo));
    return u;
}
__device__ __forceinline__ void split_bf16(float x0, float x1, unsigned& uh, unsigned& um) {
    uh = pack_bf16x2(x0, x1);
    float h0 = __uint_as_float(uh << 16);
    float h1 = __uint_as_float(uh & 0xFFFF0000u);
    um = pack_bf16x2(x0 - h0, x1 - h1);
}
__device__ __forceinline__ void mma_bf16(float* c, unsigned a0, unsigned a1, unsigned a2,
                                         unsigned a3, unsigned b0, unsigned b1) {
    asm volatile(
        "mma.sync.aligned.m16n8k16.row.col.f32.bf16.bf16.f32 "
        "{%0,%1,%2,%3}, {%4,%5,%6,%7}, {%8,%9}, {%0,%1,%2,%3};"
        : "+f"(c[0]), "+f"(c[1]), "+f"(c[2]), "+f"(c[3])
        : "r"(a0), "r"(a1), "r"(a2), "r"(a3), "r"(b0), "r"(b1));
}

// ---------------- kernel 1: projections + fused bf16 split (one mat per CTA) ----------------
__global__ __launch_bounds__(256) void proj_kernel(
    const float* __restrict__ x,
    const float* __restrict__ Wl,  const float* __restrict__ bl,
    const float* __restrict__ Wl2, const float* __restrict__ bl2)
{
    __shared__ float xs[8 * DD];
    __shared__ float ws[32 * 129];
    __shared__ float ys[8 * DD];
    const int t = threadIdx.x, l0 = blockIdx.x * 8;
    const int mat = blockIdx.y;
    const int dloc = t & 31, lrow = t >> 5;
    for (int i = t; i < 8 * DD; i += 256) xs[i] = x[l0 * DD + i];

    const float* W    = mat ? Wl2 : Wl;
    const float* bias = mat ? bl2 : bl;
    float*       outp = mat ? g_tx : g_a;
    unsigned*    oh   = mat ? g_bh : g_ah;
    unsigned*    om   = mat ? g_bm : g_am;
    for (int dc = 0; dc < 4; dc++) {
        const int d0 = dc * 32;
        __syncthreads();
        for (int i = t; i < 32 * DD; i += 256) {
            int r = i >> 7, c = i & 127;
            ws[r * 129 + c] = W[(d0 + r) * DD + c];
        }
        __syncthreads();
        float acc = 0.f;
        #pragma unroll 8
        for (int c = 0; c < DD; c++) acc += xs[lrow * DD + c] * ws[dloc * 129 + c];
        acc += bias[d0 + dloc];
        outp[(l0 + lrow) * DD + d0 + dloc] = acc;
        ys[lrow * DD + d0 + dloc] = acc;
    }
    __syncthreads();
    #pragma unroll
    for (int i = 0; i < 2; i++) {
        int idx = t + 256 * i;
        int j = idx >> 7, c = idx & 127;
        float x0 = ys[(2 * j) * DD + c];
        float x1 = ys[(2 * j + 1) * DD + c];
        unsigned uh, um; split_bf16(x0, x1, uh, um);
        int kp = (l0 >> 1) + j;
        oh[kp * DD + c] = uh; om[kp * DD + c] = um;
    }
}

// ---------------- kernel 2: R partials (16 m-groups of 64) + mask pair-words + ctr reset ----------------
__global__ __launch_bounds__(256) void r_kernel(const int* __restrict__ mask)
{
    __shared__ float s_txc[64 * DD];
    __shared__ float s_mk [16 * 64];
    const int t = threadIdx.x;
    const int l0 = blockIdx.x * 16;
    const int mg = blockIdx.y;
    const int m0 = mg * 64;
    const int d4 = t & 31, lg = t >> 5;
    if (blockIdx.x == 0 && mg == 0 && t == 0) g_tile_ctr = 0u;

    // mask pair-words for this (l-tile, m-group): 16 l x 32 kp
    #pragma unroll
    for (int i = 0; i < 2; i++) {
        int idx = t + 256 * i;                 // 0..511
        int li = idx >> 5, kpl = idx & 31;
        int kp = mg * 32 + kpl;
        int ma = mask[(l0 + li) * LLEN + 2 * kp];
        int mb = mask[(l0 + li) * LLEN + 2 * kp + 1];
        g_mkp[(l0 + li) * 512 + kp] = (ma ? 0x0000FFFFu : 0u) | (mb ? 0xFFFF0000u : 0u);
    }

    // stage tx rows + mask floats
    #pragma unroll
    for (int r = 0; r < 8; r++) {
        int idx = t + 256 * r;
        int rw = idx >> 5, c4 = idx & 31;
        *(float4*)&s_txc[rw * DD + c4 * 4] = *(const float4*)&g_tx[(m0 + rw) * DD + c4 * 4];
    }
    #pragma unroll
    for (int r = 0; r < 4; r++) {
        int idx = t + 256 * r;
        int li = idx >> 6, mm = idx & 63;
        s_mk[li * 64 + mm] = (mask[(l0 + li) * LLEN + m0 + mm] != 0) ? 1.f : 0.f;
    }
    __syncthreads();

    float4 a0 = {0.f,0.f,0.f,0.f}, a1 = {0.f,0.f,0.f,0.f};
    #pragma unroll 4
    for (int mm = 0; mm < 64; mm++) {
        float4 tv = *(float4*)&s_txc[mm * DD + d4 * 4];
        float f0 = s_mk[(lg * 2) * 64 + mm];
        float f1 = s_mk[(lg * 2 + 1) * 64 + mm];
        a0.x += tv.x * f0; a0.y += tv.y * f0; a0.z += tv.z * f0; a0.w += tv.w * f0;
        a1.x += tv.x * f1; a1.y += tv.y * f1; a1.z += tv.z * f1; a1.w += tv.w * f1;
    }
    *(float4*)&g_Rp[(mg * LLEN + l0 + lg * 2) * DD + d4 * 4]     = a0;
    *(float4*)&g_Rp[(mg * LLEN + l0 + lg * 2 + 1) * DD + d4 * 4] = a1;
}

// ---------------- kernel 3: persistent GEMM, 2 CTAs/SM, LP=2, KC=32, cp.async.ca ----------------
// (verified R10 kernel, unchanged)
__global__ __launch_bounds__(256, 2) void cop_kernel(const float* __restrict__ Wlo)
{
    extern __shared__ char sm[];
    float*    s_a   = (float*)sm;
    unsigned* s_mk  = (unsigned*)(sm + 1024);
    float*    s_wlo = (float*)(sm + 5120);
    float*    s_ep  = (float*)(sm + 38912);
    __shared__ int s_tile;
    const unsigned sb = smem_u32(sm);

    const int t    = threadIdx.x;
    const int w    = t >> 5;
    const int lane = t & 31;
    const int gid  = lane >> 2;
    const int tig  = lane & 3;
    const int ct0  = w * 16;

    for (;;) {
        if (t == 0) s_tile = (int)atomicAdd(&g_tile_ctr, 1u);
        __syncthreads();
        const int tile = s_tile;
        if (tile >= NTILE) break;
        const int l0 = (tile >> 1) * LP;
        const int d0 = (tile & 1) * 64;

        if (t < LP * DD) s_a[t] = g_a[(l0 + (t >> 7)) * DD + (t & 127)];
        #pragma unroll
        for (int i = 0; i < 4; i++) {
            int idx = t + 256 * i;
            s_mk[idx] = g_mkp[(l0 + (idx >> 9)) * 512 + (idx & 511)];
        }

        float acc[LP][8][4];
        #pragma unroll
        for (int l = 0; l < LP; l++)
            #pragma unroll
            for (int dg = 0; dg < 8; dg++)
                #pragma unroll
                for (int q = 0; q < 4; q++) acc[l][dg][q] = 0.f;

        {
            const unsigned bufu = sb + 5120;
            #pragma unroll
            for (int i = 0; i < 2; i++) {
                int idx = t + 256 * i;
                int rw = idx >> 5, c4 = idx & 31;
                const unsigned dsto = (rw * 136 + c4 * 4) * 4;
                CP_ASYNC16(bufu + dsto,        (const char*)(g_ah + rw * 128 + c4 * 4));
                CP_ASYNC16(bufu + 8704 + dsto, (const char*)(g_am + rw * 128 + c4 * 4));
            }
            {
                int rw = t >> 4, c4 = t & 15;
                const unsigned dsto = (rw * 72 + c4 * 4) * 4;
                CP_ASYNC16(bufu + 17408 + dsto, (const char*)(g_bh + rw * 128 + d0 + c4 * 4));
                CP_ASYNC16(bufu + 22016 + dsto, (const char*)(g_bm + rw * 128 + d0 + c4 * 4));
            }
            CP_COMMIT();
        }

        #pragma unroll 1
        for (int r = 0; r < 32; r++) {
            CP_WAIT0();
            __syncthreads();
            if (r < 31) {
                const int kg = (r + 1) * 16;
                const unsigned bufu = sb + 5120 + ((r + 1) & 1) * BUFB;
                #pragma unroll
                for (int i = 0; i < 2; i++) {
                    int idx = t + 256 * i;
                    int rw = idx >> 5, c4 = idx & 31;
                    const unsigned dsto = (rw * 136 + c4 * 4) * 4;
                    const unsigned srco = (kg + rw) * 128 + c4 * 4;
                    CP_ASYNC16(bufu + dsto,        (const char*)(g_ah + srco));
                    CP_ASYNC16(bufu + 8704 + dsto, (const char*)(g_am + srco));
                }
                {
                    int rw = t >> 4, c4 = t & 15;
                    const unsigned dsto = (rw * 72 + c4 * 4) * 4;
                    const unsigned srco = (kg + rw) * 128 + d0 + c4 * 4;
                    CP_ASYNC16(bufu + 17408 + dsto, (const char*)(g_bh + srco));
                    CP_ASYNC16(bufu + 22016 + dsto, (const char*)(g_bm + srco));
                }
                CP_COMMIT();
            }
            char* buf = sm + 5120 + (r & 1) * BUFB;
            unsigned* sAh = (unsigned*)(buf);
            unsigned* sAm = (unsigned*)(buf + 8704);
            unsigned* sBh = (unsigned*)(buf + 17408);
            unsigned* sBm = (unsigned*)(buf + 22016);
            const int kpg = r * 16;
            #pragma unroll
            for (int s = 0; s < 2; s++) {
                const int kb = 8 * s;
                unsigned ah0 = sAh[(kb + tig) * 136 + ct0 + gid];
                unsigned ah1 = sAh[(kb + tig) * 136 + ct0 + gid + 8];
                unsigned ah2 = sAh[(kb + tig + 4) * 136 + ct0 + gid];
                unsigned ah3 = sAh[(kb + tig + 4) * 136 + ct0 + gid + 8];
                unsigned am0 = sAm[(kb + tig) * 136 + ct0 + gid];
                unsigned am1 = sAm[(kb + tig) * 136 + ct0 + gid + 8];
                unsigned am2 = sAm[(kb + tig + 4) * 136 + ct0 + gid];
                unsigned am3 = sAm[(kb + tig + 4) * 136 + ct0 + gid + 8];
                unsigned mkl[LP], mkh[LP];
                #pragma unroll
                for (int l = 0; l < LP; l++) {
                    mkl[l] = s_mk[l * 512 + kpg + kb + tig];
                    mkh[l] = s_mk[l * 512 + kpg + kb + tig + 4];
                }
                unsigned b0[8], b1[8];
                #pragma unroll
                for (int dg = 0; dg < 8; dg++) {
                    b0[dg] = sBh[(kb + tig) * 72 + dg * 8 + gid];
                    b1[dg] = sBh[(kb + tig + 4) * 72 + dg * 8 + gid];
                }
                #pragma unroll
                for (int l = 0; l < LP; l++) {      // hh
                    unsigned x0 = ah0 & mkl[l], x1 = ah1 & mkl[l];
                    unsigned x2 = ah2 & mkh[l], x3 = ah3 & mkh[l];
                    #pragma unroll
                    for (int dg = 0; dg < 8; dg++)
                        mma_bf16(acc[l][dg], x0, x1, x2, x3, b0[dg], b1[dg]);
                }
                #pragma unroll
                for (int l = 0; l < LP; l++) {      // mh
                    unsigned x0 = am0 & mkl[l], x1 = am1 & mkl[l];
                    unsigned x2 = am2 & mkh[l], x3 = am3 & mkh[l];
                    #pragma unroll
                    for (int dg = 0; dg < 8; dg++)
                        mma_bf16(acc[l][dg], x0, x1, x2, x3, b0[dg], b1[dg]);
                }
                #pragma unroll
                for (int dg = 0; dg < 8; dg++) {
                    b0[dg] = sBm[(kb + tig) * 72 + dg * 8 + gid];
                    b1[dg] = sBm[(kb + tig + 4) * 72 + dg * 8 + gid];
                }
                #pragma unroll
                for (int l = 0; l < LP; l++) {      // hm
                    unsigned x0 = ah0 & mkl[l], x1 = ah1 & mkl[l];
                    unsigned x2 = ah2 & mkh[l], x3 = ah3 & mkh[l];
                    #pragma unroll
                    for (int dg = 0; dg < 8; dg++)
                        mma_bf16(acc[l][dg], x0, x1, x2, x3, b0[dg], b1[dg]);
                }
            }
        }

        // ---- epilogue ----
        __syncthreads();
        #pragma unroll
        for (int i = 0; i < 8; i++) {
            int idx = t + 256 * i;
            int dd = idx >> 5, c4 = idx & 31;
            *(float4*)&s_wlo[dd * 132 + c4 * 4] = *(const float4*)&Wlo[(d0 + dd) * DD + c4 * 4];
        }
        __syncthreads();

        const int cA = ct0 + gid, cB = cA + 8;
        #pragma unroll
        for (int l = 0; l < LP; l++) {
            const float aA = s_a[l * DD + cA];
            const float aB = s_a[l * DD + cB];
            float pd[16];
            #pragma unroll
            for (int dg = 0; dg < 8; dg++) {
                const int dl0 = dg * 8 + 2 * tig;
                float w0  = s_wlo[dl0 * 132 + cA],  w1  = s_wlo[(dl0 + 1) * 132 + cA];
                float w0b = s_wlo[dl0 * 132 + cB],  w1b = s_wlo[(dl0 + 1) * 132 + cB];
                pd[2 * dg]     = acc[l][dg][0] * (aA * w0) + acc[l][dg][2] * (aB * w0b);
                pd[2 * dg + 1] = acc[l][dg][1] * (aA * w1) + acc[l][dg][3] * (aB * w1b);
            }
            #pragma unroll
            for (int off = 16; off >= 4; off >>= 1)
                #pragma unroll
                for (int q = 0; q < 16; q++)
                    pd[q] += __shfl_down_sync(0xffffffffu, pd[q], off);
            if (lane < 4) {
                #pragma unroll
                for (int dg = 0; dg < 8; dg++) {
                    s_ep[w * 128 + l * 64 + dg * 8 + 2 * lane]     = pd[2 * dg];
                    s_ep[w * 128 + l * 64 + dg * 8 + 2 * lane + 1] = pd[2 * dg + 1];
                }
            }
        }
        __syncthreads();
        if (t < 128) {
            const int l = t >> 6, dloc = t & 63;
            float v = s_ep[t] + s_ep[128 + t] + s_ep[256 + t] + s_ep[384 + t]
                    + s_ep[512 + t] + s_ep[640 + t] + s_ep[768 + t] + s_ep[896 + t];
            g_o1[(l0 + l) * DD + d0 + dloc] = v;
        }
    }
}

// ---------------- kernel 4: residual + blo*R + LayerNorm ----------------
__global__ __launch_bounds__(128) void ln_kernel(
    const float* __restrict__ x,   const float* __restrict__ blo,
    const float* __restrict__ gamma, const float* __restrict__ beta,
    float* __restrict__ out)
{
    __shared__ float w1[4], w2[4];
    __shared__ float mu_s, rstd_s;
    const int l = blockIdx.x;
    const int d = threadIdx.x;
    float Rv = 0.f;
    #pragma unroll
    for (int p = 0; p < NRP; p++) Rv += g_Rp[(p * LLEN + l) * DD + d];
    float y = x[l * DD + d] + g_o1[l * DD + d] + blo[d] * Rv;
    float s1 = y, s2 = y * y;
    #pragma unroll
    for (int off = 16; off > 0; off >>= 1) {
        s1 += __shfl_down_sync(0xffffffffu, s1, off);
        s2 += __shfl_down_sync(0xffffffffu, s2, off);
    }
    const int wid = d >> 5, lid = d & 31;
    if (lid == 0) { w1[wid] = s1; w2[wid] = s2; }
    __syncthreads();
    if (d == 0) {
        float t1 = w1[0] + w1[1] + w1[2] + w1[3];
        float t2 = w2[0] + w2[1] + w2[2] + w2[3];
        float mu = t1 * (1.f / DD);
        float var = t2 * (1.f / DD) - mu * mu;
        mu_s = mu; rstd_s = rsqrtf(var + EPSF);
    }
    __syncthreads();
    out[l * DD + d] = (y - mu_s) * rstd_s * gamma[d] + beta[d];
}

// ---------------- launch ----------------
extern "C" void kernel_launch(void* const* d_in, const int* in_sizes, int n_in,
                              void* d_out, int out_size)
{
    (void)in_sizes; (void)n_in; (void)out_size;
    const float* x     = (const float*)d_in[0];
    const int*   mask  = (const int*)  d_in[1];
    const float* Wl    = (const float*)d_in[2];
    const float* bl    = (const float*)d_in[3];
    const float* Wlo   = (const float*)d_in[4];
    const float* blo   = (const float*)d_in[5];
    const float* Wl2   = (const float*)d_in[6];
    const float* bl2   = (const float*)d_in[7];
    const float* gamma = (const float*)d_in[8];
    const float* beta  = (const float*)d_in[9];
    float* out = (float*)d_out;

    static int smem_set = 0;
    if (!smem_set) {
        cudaFuncSetAttribute(cop_kernel, cudaFuncAttributeMaxDynamicSharedMemorySize, 58368);
        smem_set = 1;
    }

    proj_kernel<<<dim3(128, 2), 256>>>(x, Wl, bl, Wl2, bl2);   // 1
    r_kernel<<<dim3(64, 16), 256>>>(mask);                     // 2
    cop_kernel<<<296, 256, 58368>>>(Wlo);                      // 3
    ln_kernel<<<1024, 128>>>(x, blo, gamma, beta, out);        // 4
}